// round 15
// baseline (speedup 1.0000x reference)
#include <cuda_runtime.h>
#include <cuda_bf16.h>
#include <mma.h>
#include <cstdint>
#include <math.h>

// ---------------------------------------------------------------------------
// InverseNet_for_STL — round 15: WMMA bf16x3 tensor-core convs, N-tile 128.
// vs round 14 (passed, 13.8ms): pixel tile 64->128 (A staging amortized 2x,
// half the CTAs/barriers), uint4-vectorized A staging. Same math, same
// parity-fixed staging, same split-K policy.
// ---------------------------------------------------------------------------

using namespace nvcuda;

#define EPI_NONE   0
#define EPI_SHRINK 1
#define EPI_RES    2
#define EPI_TANH   3
#define MU_C  0.1f
#define THR_C (0.1f*0.1f)

#define BIGN 9437184
__device__ float g_z1[BIGN];
__device__ float g_z2[BIGN];
__device__ float g_z3[BIGN];
__device__ float g_r [BIGN];
__device__ float g_act[BIGN];
__device__ float g_wn[12323840];
__device__ float g_split[9437184];
__device__ __nv_bfloat16 g_wh[12323840];
__device__ __nv_bfloat16 g_wl[12323840];
__device__ __nv_bfloat16 g_wth[11141120];
__device__ __nv_bfloat16 g_wtl[11141120];

__device__ __forceinline__ float apply_epi(float r, const float* add, size_t idx, int epi)
{
    if (epi == EPI_SHRINK) {
        float ad = add ? add[idx] : 0.f;
        r = fmaxf(MU_C * r + ad - THR_C, 0.f);
    } else if (epi == EPI_RES) r = add[idx] - r;
    else if (epi == EPI_TANH)  r = tanhf(r);
    return r;
}

// smem layout (bytes): meta int4[128] @0 (2048); then A hi/lo and B hi/lo,
// double buffered, bf16 LDM=40 (80B rows, 16B-aligned). fp32 epilogue
// staging (128x128) overlays offset 2048 after the mainloop.
#define LDM 40
#define AHOFF(b) (2048  + (b) * 40960)
#define ALOFF(b) (12288 + (b) * 40960)
#define BHOFF(b) (22528 + (b) * 40960)
#define BLOFF(b) (32768 + (b) * 40960)
#define SMEM_WM 83968

// ---------------------------------------------------------------------------
// Stage one K=32 chunk into smem buffer `buf`.
// A: weights bf16 hi/lo (fwd: [C2][Kdim]; convT: [par][C2][Kdim]), 128 rows,
//    uint4-vectorized (Kdim and k offsets are multiples of 8).
// B: activation gather (fp32 -> hi/lo bf16), 128 pixels x 32 k.
// ---------------------------------------------------------------------------
__device__ __forceinline__ void stage_chunk(
    char* smem, int buf, int kc, int Kdim,
    const float* __restrict__ in,
    const __nv_bfloat16* __restrict__ wA, const __nv_bfloat16* __restrict__ wAl,
    int m0, int C2, int mode, int par, int a, int bb,
    int H1, int W1, int HW1, const int4* meta, int tid)
{
    __nv_bfloat16* Ah = (__nv_bfloat16*)(smem + AHOFF(buf));
    __nv_bfloat16* Al = (__nv_bfloat16*)(smem + ALOFF(buf));
    __nv_bfloat16* Bh = (__nv_bfloat16*)(smem + BHOFF(buf));
    __nv_bfloat16* Bl = (__nv_bfloat16*)(smem + BLOFF(buf));

    // ---- A: 128 rows x 32 k = 512 uint4 (8 bf16 each) per array; 2/thread.
#pragma unroll
    for (int s2 = 0; s2 < 2; s2++) {
        int slot = tid * 2 + s2;            // 0..511
        int r = slot >> 2;                  // row 0..127
        int klb = (slot & 3) * 8;           // 0,8,16,24
        int k = kc + klb;
        uint4 vh = make_uint4(0u, 0u, 0u, 0u), vl = vh;
        if ((m0 + r) < C2 && k + 8 <= Kdim) {
            const size_t rowoff =
                (mode ? ((size_t)par * C2 + (m0 + r)) : (size_t)(m0 + r)) * Kdim;
            vh = *(const uint4*)(wA + rowoff + k);
            vl = *(const uint4*)(wAl + rowoff + k);
        }
        *(uint4*)&Ah[r * LDM + klb] = vh;
        *(uint4*)&Al[r * LDM + klb] = vl;
    }
    // ---- B: 128 px x 32 k, per-element gather; thread = (px, 16-k half)
    {
        const int px = tid & 127;
        const int kb = (tid >> 7) * 16;
        int4 m = meta[px];
#pragma unroll
        for (int i = 0; i < 16; i++) {
            int kl = kb + i;
            int k = kc + kl;
            float v = 0.f;
            if (m.w >= 0 && k < Kdim) {
                if (!mode) {
                    int ci = k >> 4, rr = k & 15, kh = rr >> 2, kw = rr & 3;
                    int ih = m.y + kh, iw = m.z + kw;
                    if ((unsigned)ih < (unsigned)H1 && (unsigned)iw < (unsigned)W1)
                        v = __ldg(in + m.x + ci * HW1 + ih * W1 + iw);
                } else {
                    int co = k >> 2, jj = (k >> 1) & 1, ll = k & 1;
                    int oh = m.y + a - jj, ow = m.z + bb - ll;
                    if ((unsigned)oh < (unsigned)H1 && (unsigned)ow < (unsigned)W1)
                        v = __ldg(in + m.x + co * HW1 + oh * W1 + ow);
                }
            }
            __nv_bfloat16 h = __float2bfloat16(v);
            Bh[px * LDM + kl] = h;
            Bl[px * LDM + kl] = __float2bfloat16(v - __bfloat162float(h));
        }
    }
}

// ---------------------------------------------------------------------------
// Unified WMMA conv. mode 0: fwd 4x4 s2 p1. mode 1: convT parity-decomposed
// (z = par + 4*spl). Block: 128 (C2 rows) x 128 (pixels); 8 warps (4 row
// groups x 2 px groups); warp tile 32M x 64N = 2x4 m16n16k16 frags;
// x3 mmas (hh, hl, lh).
// ---------------------------------------------------------------------------
__global__ __launch_bounds__(256) void conv_wm(
    const float* __restrict__ in,
    const __nv_bfloat16* __restrict__ wA, const __nv_bfloat16* __restrict__ wAl,
    float* __restrict__ out, const float* __restrict__ add,
    int N, int C1, int H1, int W1, int C2, int H2, int W2,
    int epi, int nch, int slab, int raw, int mode)
{
    extern __shared__ char smem[];
    int par = 0, spl = blockIdx.z;
    if (mode) { par = blockIdx.z & 3; spl = blockIdx.z >> 2; }
    const int a = par >> 1, bb = par & 1;
    const int Kdim = C1 * (mode ? 4 : 16);
    const int HW1 = H1 * W1, HW2 = H2 * W2;
    const int m0 = blockIdx.x * 128;
    const int p0 = blockIdx.y * 128;
    const int c0 = spl * nch;
    if (raw) out += (size_t)spl * slab;

    int4* meta = (int4*)smem;
    const int tid = threadIdx.x, wid = tid >> 5;
    const int wy = wid >> 1, wx = wid & 1;

    if (tid < 128) {
        int4 m;
        if (!mode) {
            int Ntot = N * HW2, p = p0 + tid;
            bool v = p < Ntot; int pp = v ? p : 0;
            int n = pp / HW2, rem = pp - n * HW2, oh = rem / W2, ow = rem - oh * W2;
            m = make_int4(n * C1 * HW1, oh * 2 - 1, ow * 2 - 1, v ? (n * C2 * HW2 + rem) : -1);
        } else {
            int HH = H2 >> 1, WW = W2 >> 1, PHW = HH * WW, Ntot = N * PHW, p = p0 + tid;
            bool v = p < Ntot; int pp = v ? p : 0;
            int n = pp / PHW, rem = pp - n * PHW, u = rem / WW, vp = rem - u * WW;
            m = make_int4(n * C1 * HW1, u, vp,
                          v ? (n * C2 * HW2 + (2 * u + a) * W2 + (2 * vp + bb)) : -1);
        }
        meta[tid] = m;
    }
    __syncthreads();

    wmma::fragment<wmma::accumulator, 16, 16, 16, float> acc[2][4];
#pragma unroll
    for (int i = 0; i < 2; i++)
#pragma unroll
        for (int j = 0; j < 4; j++) wmma::fill_fragment(acc[i][j], 0.f);

    stage_chunk(smem, 0, c0 * 32, Kdim, in, wA, wAl, m0, C2, mode, par, a, bb,
                H1, W1, HW1, meta, tid);
    __syncthreads();

    for (int c = 0; c < nch; c++) {
        const int buf = c & 1;
        if (c + 1 < nch)
            stage_chunk(smem, buf ^ 1, (c0 + c + 1) * 32, Kdim, in, wA, wAl,
                        m0, C2, mode, par, a, bb, H1, W1, HW1, meta, tid);

        const __nv_bfloat16* Ah = (const __nv_bfloat16*)(smem + AHOFF(buf));
        const __nv_bfloat16* Al = (const __nv_bfloat16*)(smem + ALOFF(buf));
        const __nv_bfloat16* Bh = (const __nv_bfloat16*)(smem + BHOFF(buf));
        const __nv_bfloat16* Bl = (const __nv_bfloat16*)(smem + BLOFF(buf));

#pragma unroll
        for (int ks = 0; ks < 32; ks += 16) {
            wmma::fragment<wmma::matrix_a, 16, 16, 16, __nv_bfloat16, wmma::row_major> ahi[2], alo[2];
#pragma unroll
            for (int i = 0; i < 2; i++) {
                wmma::load_matrix_sync(ahi[i], Ah + (wy * 32 + i * 16) * LDM + ks, LDM);
                wmma::load_matrix_sync(alo[i], Al + (wy * 32 + i * 16) * LDM + ks, LDM);
            }
#pragma unroll
            for (int j = 0; j < 4; j++) {
                wmma::fragment<wmma::matrix_b, 16, 16, 16, __nv_bfloat16, wmma::col_major> bhi, blo;
                wmma::load_matrix_sync(bhi, Bh + (wx * 64 + j * 16) * LDM + ks, LDM);
                wmma::load_matrix_sync(blo, Bl + (wx * 64 + j * 16) * LDM + ks, LDM);
#pragma unroll
                for (int i = 0; i < 2; i++) {
                    wmma::mma_sync(acc[i][j], ahi[i], bhi, acc[i][j]);
                    wmma::mma_sync(acc[i][j], ahi[i], blo, acc[i][j]);
                    wmma::mma_sync(acc[i][j], alo[i], bhi, acc[i][j]);
                }
            }
        }
        __syncthreads();
    }

    // epilogue: frags -> smem (overlay) -> gmem with epi
    float* outsm = (float*)(smem + 2048);
#pragma unroll
    for (int i = 0; i < 2; i++)
#pragma unroll
        for (int j = 0; j < 4; j++)
            wmma::store_matrix_sync(outsm + (wy * 32 + i * 16) * 128 + wx * 64 + j * 16,
                                    acc[i][j], 128, wmma::mem_row_major);
    __syncthreads();
#pragma unroll
    for (int i = 0; i < 64; i++) {
        int lin = i * 256 + tid;
        int r = lin >> 7, px = lin & 127;
        if (m0 + r >= C2) continue;
        int4 m = meta[px];
        if (m.w < 0) continue;
        size_t idx = (size_t)m.w + (size_t)(m0 + r) * HW2;
        float f = outsm[r * 128 + px];
        out[idx] = raw ? f : apply_epi(f, add, idx, epi);
    }
}

// ---------------------------------------------------------------------------
// Split-K reduce + epilogue.
// ---------------------------------------------------------------------------
__global__ void reduce_epi_k(const float* __restrict__ sl, int S, int n4,
                             float* __restrict__ out, const float* __restrict__ add, int epi)
{
    int i = blockIdx.x * blockDim.x + threadIdx.x;
    if (i >= n4) return;
    const float4* sl4 = (const float4*)sl;
    float4 v = sl4[i];
    for (int s = 1; s < S; s++) {
        float4 t = sl4[(size_t)s * n4 + i];
        v.x += t.x; v.y += t.y; v.z += t.z; v.w += t.w;
    }
    if (epi == EPI_SHRINK) {
        float4 a = add ? ((const float4*)add)[i] : make_float4(0.f, 0.f, 0.f, 0.f);
        v.x = fmaxf(MU_C * v.x + a.x - THR_C, 0.f);
        v.y = fmaxf(MU_C * v.y + a.y - THR_C, 0.f);
        v.z = fmaxf(MU_C * v.z + a.z - THR_C, 0.f);
        v.w = fmaxf(MU_C * v.w + a.w - THR_C, 0.f);
    } else if (epi == EPI_RES) {
        float4 a = ((const float4*)add)[i];
        v.x = a.x - v.x; v.y = a.y - v.y; v.z = a.z - v.z; v.w = a.w - v.w;
    } else if (epi == EPI_TANH) {
        v.x = tanhf(v.x); v.y = tanhf(v.y); v.z = tanhf(v.z); v.w = tanhf(v.w);
    }
    ((float4*)out)[i] = v;
}

// ---------------------------------------------------------------------------
// Cin=3 transposed conv (fp32 direct).
// ---------------------------------------------------------------------------
__global__ __launch_bounds__(128) void conv_t_c3_k(
    const float* __restrict__ y, const float* __restrict__ w,
    float* __restrict__ out, const float* __restrict__ add,
    int N, int Cy, int OHy, int OWy, int H, int Wd, int epi)
{
    const int a = blockIdx.z >> 1, b = blockIdx.z & 1;
    const int HH = H >> 1, WW = Wd >> 1, PHW = HH * WW, Ntot = N * PHW;
    const int OHWy = OHy * OWy;
    const int kha0 = 1 - a, kwb0 = 1 - b;
    __shared__ float Wsm[768];
    const int tid = threadIdx.x;
    for (int i = tid; i < Cy * 12; i += 128) {
        int co = i / 12, r = i - co * 12, ci = r >> 2, jj = (r >> 1) & 1, ll = r & 1;
        Wsm[i] = w[(((size_t)co * 3 + ci) * 4 + (kha0 + 2 * jj)) * 4 + (kwb0 + 2 * ll)];
    }
    __syncthreads();
    int p = blockIdx.x * 128 + tid;
    if (p >= Ntot) return;
    int n = p / PHW, rem = p - n * PHW, u = rem / WW, v = rem - u * WW;
    float acc0 = 0.f, acc1 = 0.f, acc2 = 0.f;
    const int oh0 = u + a, oh1 = u + a - 1, ow0 = v + b, ow1 = v + b - 1;
    const bool h0 = (unsigned)oh0 < (unsigned)OHy, h1 = (unsigned)oh1 < (unsigned)OHy;
    const bool w0 = (unsigned)ow0 < (unsigned)OWy, w1 = (unsigned)ow1 < (unsigned)OWy;
    const float* ybase = y + (size_t)n * Cy * OHWy;
    for (int co = 0; co < Cy; co++) {
        const float* yc = ybase + (size_t)co * OHWy;
        const float* wc = &Wsm[co * 12];
        float y00 = (h0 && w0) ? yc[oh0 * OWy + ow0] : 0.f;
        float y01 = (h0 && w1) ? yc[oh0 * OWy + ow1] : 0.f;
        float y10 = (h1 && w0) ? yc[oh1 * OWy + ow0] : 0.f;
        float y11 = (h1 && w1) ? yc[oh1 * OWy + ow1] : 0.f;
        acc0 += y00 * wc[0] + y01 * wc[1] + y10 * wc[2] + y11 * wc[3];
        acc1 += y00 * wc[4] + y01 * wc[5] + y10 * wc[6] + y11 * wc[7];
        acc2 += y00 * wc[8] + y01 * wc[9] + y10 * wc[10] + y11 * wc[11];
    }
    const int HWi = H * Wd;
    size_t ob = (size_t)n * 3 * HWi + (size_t)(2 * u + a) * Wd + (2 * v + b);
    float accs[3] = {acc0, acc1, acc2};
#pragma unroll
    for (int ci = 0; ci < 3; ci++) {
        size_t idx = ob + (size_t)ci * HWi;
        out[idx] = apply_epi(accs[ci], add, idx, epi);
    }
}

// ---------------------------------------------------------------------------
// Block-6 GEMV / GEMM-T (fp32)
// ---------------------------------------------------------------------------
__global__ __launch_bounds__(256) void gemv6_k(
    const float* __restrict__ in, const float* __restrict__ w,
    float* __restrict__ out, const float* __restrict__ add, int epi)
{
    __shared__ float xs[9216];
    const int n = blockIdx.x;
    const float* xr = in + (size_t)n * 9216;
    for (int i = threadIdx.x; i < 9216; i += 256) xs[i] = xr[i];
    __syncthreads();
    const int warp = threadIdx.x >> 5, lane = threadIdx.x & 31;
    const int co = blockIdx.y * 8 + warp;
    const float* wr = w + (size_t)co * 9216;
    float s = 0.f;
    for (int k = lane; k < 9216; k += 32) s += xs[k] * wr[k];
#pragma unroll
    for (int o = 16; o; o >>= 1) s += __shfl_down_sync(0xffffffffu, s, o);
    if (lane == 0) {
        int idx = n * 128 + co;
        float v = s;
        if (epi == EPI_SHRINK) {
            float ad = add ? add[idx] : 0.f;
            v = fmaxf(MU_C * v + ad - THR_C, 0.f);
        }
        out[idx] = v;
    }
}

__global__ __launch_bounds__(256) void gemm6t_k(
    const float* __restrict__ h, const float* __restrict__ w,
    float* __restrict__ out, const float* __restrict__ add, int epi)
{
    __shared__ float hs[128];
    const int n = blockIdx.y;
    const int m = blockIdx.x * 1024 + threadIdx.x * 4;
    if (threadIdx.x < 128) hs[threadIdx.x] = h[n * 128 + threadIdx.x];
    __syncthreads();
    float4 acc = make_float4(0.f, 0.f, 0.f, 0.f);
    const float* wp = w + m;
#pragma unroll 4
    for (int co = 0; co < 128; co++) {
        float hv = hs[co];
        float4 wv = *(const float4*)(wp + (size_t)co * 9216);
        acc.x += hv * wv.x; acc.y += hv * wv.y;
        acc.z += hv * wv.z; acc.w += hv * wv.w;
    }
    size_t base = (size_t)n * 9216 + m;
    float r[4] = {acc.x, acc.y, acc.z, acc.w};
#pragma unroll
    for (int t = 0; t < 4; t++) {
        float v = r[t];
        if (epi == EPI_RES) v = add[base + t] - v;
        out[base + t] = v;
    }
}

// ---------------------------------------------------------------------------
// elementwise / reductions / weight prep
// ---------------------------------------------------------------------------
__global__ void fista_y_k(const float* __restrict__ z, const float* __restrict__ zold,
                          float c, float* __restrict__ y, int nelem)
{
    int i = blockIdx.x * blockDim.x + threadIdx.x;
    if (i < nelem) {
        float zv = z[i];
        y[i] = zv + c * (zv - zold[i]);
    }
}

__global__ void lrelu_k(const float* __restrict__ in, float* __restrict__ out, int n)
{
    int i = blockIdx.x * blockDim.x + threadIdx.x;
    if (i < n) {
        float v = in[i];
        out[i] = v >= 0.f ? v : 0.2f * v;
    }
}

__global__ __launch_bounds__(256) void bn_act_k(
    const float* __restrict__ in, float* __restrict__ out,
    int N, int C, int HW, int act)
{
    const int c = blockIdx.x;
    const int M = N * HW;
    const int tid = threadIdx.x;
    double ds = 0.0, ds2 = 0.0;
    for (int i = tid; i < M; i += 256) {
        int n = i / HW, r = i - n * HW;
        float v = in[((size_t)n * C + c) * HW + r];
        ds += v; ds2 += (double)v * v;
    }
    __shared__ double sh[512];
    sh[tid] = ds; sh[256 + tid] = ds2;
    __syncthreads();
    for (int s = 128; s > 0; s >>= 1) {
        if (tid < s) { sh[tid] += sh[tid + s]; sh[256 + tid] += sh[256 + tid + s]; }
        __syncthreads();
    }
    __shared__ float mean_s, scale_s;
    if (tid == 0) {
        double m = sh[0] / M;
        double var = sh[256] / M - m * m;
        float vf = (float)var; if (vf < 0.f) vf = 0.f;
        mean_s = (float)m;
        scale_s = 1.0f / sqrtf(vf + 1e-5f);
    }
    __syncthreads();
    float mean = mean_s, scale = scale_s;
    for (int i = tid; i < M; i += 256) {
        int n = i / HW, r = i - n * HW;
        size_t idx = ((size_t)n * C + c) * HW + r;
        float v = (in[idx] - mean) * scale;
        if (act == 1) v = v >= 0.f ? v : 0.2f * v;
        else if (act == 2) v = fmaxf(v, 0.f);
        out[idx] = v;
    }
}

__global__ __launch_bounds__(256) void wnorm_all_k(
    const float* __restrict__ W1, const float* __restrict__ W2,
    const float* __restrict__ W3, const float* __restrict__ W4,
    const float* __restrict__ W5, const float* __restrict__ W6,
    float* __restrict__ wn)
{
    const int a = blockIdx.x;  // 0..2111
    const int cum[6]  = {64, 192, 448, 960, 1984, 2112};
    const int lens[6] = {48, 1024, 2048, 4096, 8192, 9216};
    const long offs[6] = {0, 3072, 134144, 658432, 2755584, 11144192};
    int wi = 0;
    while (a >= cum[wi]) wi++;
    int local = a - (wi ? cum[wi - 1] : 0);
    const float* Ws[6] = {W1, W2, W3, W4, W5, W6};
    const int L = lens[wi];
    const float* src = Ws[wi] + (size_t)local * L;
    float* dst = wn + offs[wi] + (size_t)local * L;
    const int tid = threadIdx.x;
    float s = 0.f;
    for (int i = tid; i < L; i += 256) { float v = src[i]; s += v * v; }
    __shared__ float sh[256];
    sh[tid] = s; __syncthreads();
    for (int sf = 128; sf > 0; sf >>= 1) {
        if (tid < sf) sh[tid] += sh[tid + sf];
        __syncthreads();
    }
    float inv = 1.0f / (sqrtf(sh[0]) + 1e-12f);
    for (int i = tid; i < L; i += 256) dst[i] = src[i] * inv;
}

// bf16 hi/lo copies (fwd K-major) + per-parity transposed convT weights.
__global__ void wprep_k(const float* __restrict__ wn,
                        __nv_bfloat16* __restrict__ wh, __nv_bfloat16* __restrict__ wl,
                        __nv_bfloat16* __restrict__ wth, __nv_bfloat16* __restrict__ wtl)
{
    int i0 = blockIdx.x * 256 + threadIdx.x;
    int stride = gridDim.x * 256;
    for (int t = i0; t < 12323840; t += stride) {
        float v = wn[t];
        __nv_bfloat16 h = __float2bfloat16(v);
        wh[t] = h;
        wl[t] = __float2bfloat16(v - __bfloat162float(h));
    }
    const int cum[4] = {131072, 655360, 2752512, 11141120};
    const int cins[4] = {64, 128, 256, 512};
    const long woffs[4] = {3072, 134144, 658432, 2755584};
    for (int t = i0; t < 11141120; t += stride) {
        int wi = 0;
        while (t >= cum[wi]) wi++;
        int local = t - (wi ? cum[wi - 1] : 0);
        int Cin = cins[wi], Kd = 8 * Cin;   // Cout = 2*Cin -> Kdim = 4*Cout
        int per = Cin * Kd;
        int par = local / per, rem = local - par * per;
        int ci = rem / Kd, k = rem - ci * Kd;
        int co = k >> 2, jj = (k >> 1) & 1, ll = k & 1;
        int kha = 1 - (par >> 1) + 2 * jj, kwb = 1 - (par & 1) + 2 * ll;
        float v = wn[woffs[wi] + ((size_t)co * Cin + ci) * 16 + kha * 4 + kwb];
        __nv_bfloat16 h = __float2bfloat16(v);
        wth[t] = h;
        wtl[t] = __float2bfloat16(v - __bfloat162float(h));
    }
}

__global__ void znorm_k(const float* __restrict__ z, float* __restrict__ out)
{
    const int n = blockIdx.x;
    const int t = threadIdx.x;
    float v = z[n * 128 + t];
    __shared__ float sh[128];
    sh[t] = v * v; __syncthreads();
    for (int s = 64; s > 0; s >>= 1) {
        if (t < s) sh[t] += sh[t + s];
        __syncthreads();
    }
    float denom = fmaxf(sqrtf(sh[0]), 1e-12f);
    out[n * 128 + t] = v / denom;
}

// ---------------------------------------------------------------------------
// Host orchestration
// ---------------------------------------------------------------------------
static inline int cdiv(int a, int b) { return (a + b - 1) / b; }
static float* g_sp = nullptr;

static int pick_S(int base, int chunks, long nelem)
{
    int S = 1;
    while (base * S < 280 && S < 8) S <<= 1;
    while (S > 1 && (chunks % S)) S >>= 1;
    while (S > 1 && nelem * S > 9437184L) S >>= 1;
    return S;
}

static void launch_fwd(const float* in, const __nv_bfloat16* wh, const __nv_bfloat16* wl,
                       float* out, const float* add,
                       int N, int Cin, int H, int Wd, int Cout, int OH, int OW, int epi)
{
    int bx = cdiv(Cout, 128), by = cdiv(N * OH * OW, 128);
    int chunks = cdiv(Cin * 16, 32); if (chunks < 1) chunks = 1;
    long nelem = (long)N * Cout * OH * OW;
    int S = pick_S(bx * by, chunks, nelem);
    if (S == 1) {
        conv_wm<<<dim3(bx, by, 1), 256, SMEM_WM>>>(in, wh, wl, out, add,
            N, Cin, H, Wd, Cout, OH, OW, epi, chunks, 0, 0, 0);
    } else {
        conv_wm<<<dim3(bx, by, S), 256, SMEM_WM>>>(in, wh, wl, g_sp, nullptr,
            N, Cin, H, Wd, Cout, OH, OW, epi, chunks / S, (int)nelem, 1, 0);
        reduce_epi_k<<<cdiv((int)(nelem / 4), 256), 256>>>(g_sp, S, (int)(nelem / 4), out, add, epi);
    }
}

static void launch_t(const float* y, const __nv_bfloat16* wth, const __nv_bfloat16* wtl,
                     const float* wfp, float* out, const float* add,
                     int N, int Cy, int OHy, int OWy, int Cin, int H, int Wd, int epi)
{
    int NtotP = N * (H / 2) * (Wd / 2);
    if (Cin == 3) {
        conv_t_c3_k<<<dim3(cdiv(NtotP, 128), 1, 4), 128>>>(y, wfp, out, add,
            N, Cy, OHy, OWy, H, Wd, epi);
        return;
    }
    int bx = cdiv(Cin, 128), by = cdiv(NtotP, 128);
    int chunks = Cy / 8;                // Kdim(=Cy*4)/32
    long nelem = (long)N * Cin * H * Wd;
    int S = pick_S(bx * by * 4, chunks, nelem);
    if (S == 1) {
        conv_wm<<<dim3(bx, by, 4), 256, SMEM_WM>>>(y, wth, wtl, out, add,
            N, Cy, OHy, OWy, Cin, H, Wd, epi, chunks, 0, 0, 1);
    } else {
        conv_wm<<<dim3(bx, by, 4 * S), 256, SMEM_WM>>>(y, wth, wtl, g_sp, nullptr,
            N, Cy, OHy, OWy, Cin, H, Wd, epi, chunks / S, (int)nelem, 1, 1);
        reduce_epi_k<<<cdiv((int)(nelem / 4), 256), 256>>>(g_sp, S, (int)(nelem / 4), out, add, epi);
    }
}

extern "C" void kernel_launch(void* const* d_in, const int* in_sizes, int n_in,
                              void* d_out, int out_size)
{
    const float* x = (const float*)d_in[0];
    const float* W[6];
    for (int i = 0; i < 6; i++) W[i] = (const float*)d_in[1 + i];
    float* out = (float*)d_out;

    float *z1, *z2, *z3, *rb, *actb, *wn, *sp;
    __nv_bfloat16 *wh, *wl, *wth, *wtl;
    cudaGetSymbolAddress((void**)&z1, g_z1);
    cudaGetSymbolAddress((void**)&z2, g_z2);
    cudaGetSymbolAddress((void**)&z3, g_z3);
    cudaGetSymbolAddress((void**)&rb, g_r);
    cudaGetSymbolAddress((void**)&actb, g_act);
    cudaGetSymbolAddress((void**)&wn, g_wn);
    cudaGetSymbolAddress((void**)&sp, g_split);
    cudaGetSymbolAddress((void**)&wh, g_wh);
    cudaGetSymbolAddress((void**)&wl, g_wl);
    cudaGetSymbolAddress((void**)&wth, g_wth);
    cudaGetSymbolAddress((void**)&wtl, g_wtl);
    g_sp = sp;
    // conv_wm uses 82 KB dynamic smem -> raise the default 48 KB cap.
    cudaFuncSetAttribute(conv_wm, cudaFuncAttributeMaxDynamicSharedMemorySize, SMEM_WM);

    const size_t woff[6] = {0, 3072, 134144, 658432, 2755584, 11144192};
    const size_t toff[5] = {0, 0, 131072, 655360, 2752512};  // indexed by wi (1..4)

    wnorm_all_k<<<2112, 256>>>(W[0], W[1], W[2], W[3], W[4], W[5], wn);
    wprep_k<<<2048, 256>>>(wn, wh, wl, wth, wtl);

    struct Stg { int Cin, H, Cout, OH, wi; };
    const Stg st[5] = {
        {3, 96, 64, 48, 0}, {64, 48, 128, 24, 1}, {128, 24, 256, 12, 2},
        {256, 12, 512, 6, 3}, {512, 6, 1024, 3, 4},
    };

    const float* cur = x;
    for (int s = 0; s < 5; s++) {
        const Stg& S = st[s];
        const __nv_bfloat16* whp = wh + woff[S.wi];
        const __nv_bfloat16* wlp = wl + woff[S.wi];
        const int OW = S.OH, Wd = S.H;
        const int zn = 64 * S.Cout * S.OH * OW;

        launch_fwd(cur, whp, wlp, z1, nullptr, 64, S.Cin, S.H, Wd, S.Cout, S.OH, OW, EPI_SHRINK);
        float* zc = z1; float* zo = z1;
        double t = 1.0;
        for (int it = 0; it < 3; it++) {
            double tn = (1.0 + sqrt(1.0 + 4.0 * t * t)) * 0.5;
            float c = (float)((t - 1.0) / tn);
            t = tn;
            const float* yp;
            if (it == 0) yp = zc;
            else {
                fista_y_k<<<cdiv(zn, 256), 256>>>(zc, zo, c, z3, zn);
                yp = z3;
            }
            launch_t(yp, wth + toff[S.wi], wtl + toff[S.wi], wn + woff[S.wi],
                     rb, cur, 64, S.Cout, S.OH, OW, S.Cin, S.H, Wd, EPI_RES);
            float* znew = (it == 0) ? z2 : zo;
            launch_fwd(rb, whp, wlp, znew, yp, 64, S.Cin, S.H, Wd, S.Cout, S.OH, OW, EPI_SHRINK);
            zo = zc; zc = znew;
        }
        if (s == 0) lrelu_k<<<cdiv(zn, 256), 256>>>(zc, actb, zn);
        else        bn_act_k<<<S.Cout, 256>>>(zc, actb, 64, S.Cout, S.OH * OW, 1);
        cur = actb;
    }

    // block 6 (3x3 s1 p0 -> GEMM)
    {
        const float* w6 = wn + woff[5];
        const int zn = 64 * 128;
        gemv6_k<<<dim3(64, 16), 256>>>(cur, w6, z1, nullptr, EPI_SHRINK);
        float* zc = z1; float* zo = z1;
        double t = 1.0;
        for (int it = 0; it < 3; it++) {
            double tn = (1.0 + sqrt(1.0 + 4.0 * t * t)) * 0.5;
            float c = (float)((t - 1.0) / tn);
            t = tn;
            const float* yp;
            if (it == 0) yp = zc;
            else {
                fista_y_k<<<cdiv(zn, 256), 256>>>(zc, zo, c, z3, zn);
                yp = z3;
            }
            gemm6t_k<<<dim3(9, 64), 256>>>(yp, w6, rb, cur, EPI_RES);
            float* znew = (it == 0) ? z2 : zo;
            gemv6_k<<<dim3(64, 16), 256>>>(rb, w6, znew, yp, EPI_SHRINK);
            zo = zc; zc = znew;
        }
        znorm_k<<<64, 128>>>(zc, out);
    }

    // decoder
    {
        const float* w6 = wn + woff[5];
        gemm6t_k<<<dim3(9, 64), 256>>>(out, w6, z1, nullptr, EPI_NONE);
        bn_act_k<<<1024, 256>>>(z1, z1, 64, 1024, 9, 2);

        struct DS { int Cy, OHy, Cin, H, wi; };
        const DS ds[4] = {
            {1024, 3, 512, 6, 4}, {512, 6, 256, 12, 3},
            {256, 12, 128, 24, 2}, {128, 24, 64, 48, 1},
        };
        float* hin = z1; float* hout = z2;
        for (int i = 0; i < 4; i++) {
            const DS& D = ds[i];
            launch_t(hin, wth + toff[D.wi], wtl + toff[D.wi], wn + woff[D.wi],
                     hout, nullptr, 64, D.Cy, D.OHy, D.OHy, D.Cin, D.H, D.H, EPI_NONE);
            bn_act_k<<<D.Cin, 256>>>(hout, hout, 64, D.Cin, D.H * D.H, 2);
            float* tmp = hin; hin = hout; hout = tmp;
        }
        launch_t(hin, nullptr, nullptr, wn + woff[0], out + 8192, nullptr,
                 64, 64, 48, 48, 3, 96, 96, EPI_TANH);
    }
}

// round 17
// speedup vs baseline: 1.6473x; 1.6473x over previous
#include <cuda_runtime.h>
#include <cuda_bf16.h>
#include <mma.h>
#include <cstdint>
#include <math.h>

// ---------------------------------------------------------------------------
// InverseNet_for_STL — round 17 (byte-identical resubmission of round 16
// after broker-level container failure). WMMA bf16x3 tensor-core convs.
// Round-14 geometry (128M x 64N tile, 61KB smem, 3 CTA/SM — best passing
// config) + two staging optimizations:
//   * paired B-gather: even-k pairs share index math (fwd: adjacent iw;
//     convT: ll=0/1 adjacent ow), one unsigned smem store per pair
//   * uint4-vectorized A staging
// Same math, same parity-fixed weights, same split-K policy as round 14.
// ---------------------------------------------------------------------------

using namespace nvcuda;

#define EPI_NONE   0
#define EPI_SHRINK 1
#define EPI_RES    2
#define EPI_TANH   3
#define MU_C  0.1f
#define THR_C (0.1f*0.1f)

#define BIGN 9437184
__device__ float g_z1[BIGN];
__device__ float g_z2[BIGN];
__device__ float g_z3[BIGN];
__device__ float g_r [BIGN];
__device__ float g_act[BIGN];
__device__ float g_wn[12323840];
__device__ float g_split[9437184];
__device__ __nv_bfloat16 g_wh[12323840];
__device__ __nv_bfloat16 g_wl[12323840];
__device__ __nv_bfloat16 g_wth[11141120];
__device__ __nv_bfloat16 g_wtl[11141120];

__device__ __forceinline__ float apply_epi(float r, const float* add, size_t idx, int epi)
{
    if (epi == EPI_SHRINK) {
        float ad = add ? add[idx] : 0.f;
        r = fmaxf(MU_C * r + ad - THR_C, 0.f);
    } else if (epi == EPI_RES) r = add[idx] - r;
    else if (epi == EPI_TANH)  r = tanhf(r);
    return r;
}

__device__ __forceinline__ unsigned pack_bf2(float v0, float v1)
{
    __nv_bfloat16 h0 = __float2bfloat16(v0), h1 = __float2bfloat16(v1);
    return (unsigned)__bfloat16_as_ushort(h0) | ((unsigned)__bfloat16_as_ushort(h1) << 16);
}

// smem layout (bytes): meta int4[64] @0; A hi/lo + B hi/lo double-buffered,
// bf16 with leading dim 40; fp32 output staging overlays A after the loop.
#define LDM 40
#define AHOFF(b) (1024 + (b) * 10240)
#define ALOFF(b) (21504 + (b) * 10240)
#define BHOFF(b) (41984 + (b) * 5120)
#define BLOFF(b) (52224 + (b) * 5120)
#define SMEM_WM 62464

// ---------------------------------------------------------------------------
// Stage one K=32 chunk into smem buffer `buf`.
// A: weights bf16 hi/lo (fwd: [C2][Kdim]; convT: [par][C2][Kdim]), 128 rows,
//    uint4-vectorized (Kdim multiple of 32, kc multiple of 32).
// B: activation gather (fp32 -> hi/lo bf16), 64 pixels x 32 k, PAIRED:
//    even k pairs share (ci,kh,ih)/(co,jj,oh); one unsigned store per pair.
// ---------------------------------------------------------------------------
__device__ __forceinline__ void stage_chunk(
    char* smem, int buf, int kc, int Kdim,
    const float* __restrict__ in,
    const __nv_bfloat16* __restrict__ wA, const __nv_bfloat16* __restrict__ wAl,
    int m0, int C2, int mode, int par, int a, int bb,
    int H1, int W1, int HW1, const int4* meta, int tid)
{
    __nv_bfloat16* Ah = (__nv_bfloat16*)(smem + AHOFF(buf));
    __nv_bfloat16* Al = (__nv_bfloat16*)(smem + ALOFF(buf));
    __nv_bfloat16* Bh = (__nv_bfloat16*)(smem + BHOFF(buf));
    __nv_bfloat16* Bl = (__nv_bfloat16*)(smem + BLOFF(buf));

    // ---- A: 128 rows x 32 k = 512 uint4 (8 bf16) per array; 2 per thread.
#pragma unroll
    for (int s2 = 0; s2 < 2; s2++) {
        int slot = tid * 2 + s2;            // 0..511
        int r = slot >> 2;                  // row 0..127
        int klb = (slot & 3) * 8;           // 0,8,16,24
        int k = kc + klb;
        uint4 vh = make_uint4(0u, 0u, 0u, 0u), vl = vh;
        if ((m0 + r) < C2 && k + 8 <= Kdim) {
            const size_t rowoff =
                (mode ? ((size_t)par * C2 + (m0 + r)) : (size_t)(m0 + r)) * Kdim;
            vh = *(const uint4*)(wA + rowoff + k);
            vl = *(const uint4*)(wAl + rowoff + k);
        }
        *(uint4*)&Ah[r * LDM + klb] = vh;
        *(uint4*)&Al[r * LDM + klb] = vl;
    }
    // ---- B: 64 px x 32 k; thread = (px, 8-k group) = 4 pairs.
    {
        const int px = tid & 63;
        const int kb = (tid >> 6) * 8;      // 0,8,16,24 (even)
        int4 m = meta[px];
#pragma unroll
        for (int p2 = 0; p2 < 4; p2++) {
            int kl = kb + 2 * p2;           // even
            int k = kc + kl;
            float v0 = 0.f, v1 = 0.f;
            if (m.w >= 0 && k < Kdim) {
                if (!mode) {
                    int ci = k >> 4, rr = k & 15, kh = rr >> 2, kw = rr & 3; // kw even
                    int ih = m.y + kh;
                    if ((unsigned)ih < (unsigned)H1) {
                        const float* bp = in + m.x + ci * HW1 + ih * W1;
                        int iw = m.z + kw;
                        if ((unsigned)iw < (unsigned)W1) v0 = __ldg(bp + iw);
                        if ((unsigned)(iw + 1) < (unsigned)W1) v1 = __ldg(bp + iw + 1);
                    }
                } else {
                    int co = k >> 2, jj = (k >> 1) & 1;   // ll = 0 then 1
                    int oh = m.y + a - jj;
                    if ((unsigned)oh < (unsigned)H1) {
                        const float* bp = in + m.x + co * HW1 + oh * W1;
                        int o0 = m.z + bb, o1 = o0 - 1;
                        if ((unsigned)o0 < (unsigned)W1) v0 = __ldg(bp + o0);
                        if ((unsigned)o1 < (unsigned)W1) v1 = __ldg(bp + o1);
                    }
                }
            }
            __nv_bfloat16 h0 = __float2bfloat16(v0), h1 = __float2bfloat16(v1);
            float l0 = v0 - __bfloat162float(h0);
            float l1 = v1 - __bfloat162float(h1);
            *(unsigned*)&Bh[px * LDM + kl] =
                (unsigned)__bfloat16_as_ushort(h0) |
                ((unsigned)__bfloat16_as_ushort(h1) << 16);
            *(unsigned*)&Bl[px * LDM + kl] = pack_bf2(l0, l1);
        }
    }
}

// ---------------------------------------------------------------------------
// Unified WMMA conv. mode 0: fwd 4x4 s2 p1. mode 1: convT parity-decomposed
// (z = par + 4*spl). Block: 128 (C2 rows) x 64 (pixels); 8 warps 4x2;
// warp tile 32x32 = 2x2 m16n16k16 frags; x3 mmas (hh, hl, lh).
// ---------------------------------------------------------------------------
__global__ __launch_bounds__(256) void conv_wm(
    const float* __restrict__ in,
    const __nv_bfloat16* __restrict__ wA, const __nv_bfloat16* __restrict__ wAl,
    float* __restrict__ out, const float* __restrict__ add,
    int N, int C1, int H1, int W1, int C2, int H2, int W2,
    int epi, int nch, int slab, int raw, int mode)
{
    extern __shared__ char smem[];
    int par = 0, spl = blockIdx.z;
    if (mode) { par = blockIdx.z & 3; spl = blockIdx.z >> 2; }
    const int a = par >> 1, bb = par & 1;
    const int Kdim = C1 * (mode ? 4 : 16);
    const int HW1 = H1 * W1, HW2 = H2 * W2;
    const int m0 = blockIdx.x * 128;
    const int p0 = blockIdx.y * 64;
    const int c0 = spl * nch;
    if (raw) out += (size_t)spl * slab;

    int4* meta = (int4*)smem;
    const int tid = threadIdx.x, wid = tid >> 5;
    const int wy = wid >> 1, wx = wid & 1;

    if (tid < 64) {
        int4 m;
        if (!mode) {
            int Ntot = N * HW2, p = p0 + tid;
            bool v = p < Ntot; int pp = v ? p : 0;
            int n = pp / HW2, rem = pp - n * HW2, oh = rem / W2, ow = rem - oh * W2;
            m = make_int4(n * C1 * HW1, oh * 2 - 1, ow * 2 - 1, v ? (n * C2 * HW2 + rem) : -1);
        } else {
            int HH = H2 >> 1, WW = W2 >> 1, PHW = HH * WW, Ntot = N * PHW, p = p0 + tid;
            bool v = p < Ntot; int pp = v ? p : 0;
            int n = pp / PHW, rem = pp - n * PHW, u = rem / WW, vp = rem - u * WW;
            m = make_int4(n * C1 * HW1, u, vp,
                          v ? (n * C2 * HW2 + (2 * u + a) * W2 + (2 * vp + bb)) : -1);
        }
        meta[tid] = m;
    }
    __syncthreads();

    wmma::fragment<wmma::accumulator, 16, 16, 16, float> acc[2][2];
#pragma unroll
    for (int i = 0; i < 2; i++)
#pragma unroll
        for (int j = 0; j < 2; j++) wmma::fill_fragment(acc[i][j], 0.f);

    stage_chunk(smem, 0, c0 * 32, Kdim, in, wA, wAl, m0, C2, mode, par, a, bb,
                H1, W1, HW1, meta, tid);
    __syncthreads();

    for (int c = 0; c < nch; c++) {
        const int buf = c & 1;
        if (c + 1 < nch)
            stage_chunk(smem, buf ^ 1, (c0 + c + 1) * 32, Kdim, in, wA, wAl,
                        m0, C2, mode, par, a, bb, H1, W1, HW1, meta, tid);

        const __nv_bfloat16* Ah = (const __nv_bfloat16*)(smem + AHOFF(buf));
        const __nv_bfloat16* Al = (const __nv_bfloat16*)(smem + ALOFF(buf));
        const __nv_bfloat16* Bh = (const __nv_bfloat16*)(smem + BHOFF(buf));
        const __nv_bfloat16* Bl = (const __nv_bfloat16*)(smem + BLOFF(buf));

#pragma unroll
        for (int ks = 0; ks < 32; ks += 16) {
            wmma::fragment<wmma::matrix_a, 16, 16, 16, __nv_bfloat16, wmma::row_major> ahi[2], alo[2];
#pragma unroll
            for (int i = 0; i < 2; i++) {
                wmma::load_matrix_sync(ahi[i], Ah + (wy * 32 + i * 16) * LDM + ks, LDM);
                wmma::load_matrix_sync(alo[i], Al + (wy * 32 + i * 16) * LDM + ks, LDM);
            }
#pragma unroll
            for (int j = 0; j < 2; j++) {
                wmma::fragment<wmma::matrix_b, 16, 16, 16, __nv_bfloat16, wmma::col_major> bhi, blo;
                wmma::load_matrix_sync(bhi, Bh + (wx * 32 + j * 16) * LDM + ks, LDM);
                wmma::load_matrix_sync(blo, Bl + (wx * 32 + j * 16) * LDM + ks, LDM);
#pragma unroll
                for (int i = 0; i < 2; i++) {
                    wmma::mma_sync(acc[i][j], ahi[i], bhi, acc[i][j]);
                    wmma::mma_sync(acc[i][j], ahi[i], blo, acc[i][j]);
                    wmma::mma_sync(acc[i][j], alo[i], bhi, acc[i][j]);
                }
            }
        }
        __syncthreads();
    }

    // epilogue: frags -> smem (overlay) -> gmem with epi
    float* outsm = (float*)(smem + 1024);
#pragma unroll
    for (int i = 0; i < 2; i++)
#pragma unroll
        for (int j = 0; j < 2; j++)
            wmma::store_matrix_sync(outsm + (wy * 32 + i * 16) * 64 + wx * 32 + j * 16,
                                    acc[i][j], 64, wmma::mem_row_major);
    __syncthreads();
#pragma unroll
    for (int i = 0; i < 32; i++) {
        int lin = i * 256 + tid;
        int r = lin >> 6, px = lin & 63;
        if (m0 + r >= C2) continue;
        int4 m = meta[px];
        if (m.w < 0) continue;
        size_t idx = (size_t)m.w + (size_t)(m0 + r) * HW2;
        float f = outsm[r * 64 + px];
        out[idx] = raw ? f : apply_epi(f, add, idx, epi);
    }
}

// ---------------------------------------------------------------------------
// Split-K reduce + epilogue.
// ---------------------------------------------------------------------------
__global__ void reduce_epi_k(const float* __restrict__ sl, int S, int n4,
                             float* __restrict__ out, const float* __restrict__ add, int epi)
{
    int i = blockIdx.x * blockDim.x + threadIdx.x;
    if (i >= n4) return;
    const float4* sl4 = (const float4*)sl;
    float4 v = sl4[i];
    for (int s = 1; s < S; s++) {
        float4 t = sl4[(size_t)s * n4 + i];
        v.x += t.x; v.y += t.y; v.z += t.z; v.w += t.w;
    }
    if (epi == EPI_SHRINK) {
        float4 a = add ? ((const float4*)add)[i] : make_float4(0.f, 0.f, 0.f, 0.f);
        v.x = fmaxf(MU_C * v.x + a.x - THR_C, 0.f);
        v.y = fmaxf(MU_C * v.y + a.y - THR_C, 0.f);
        v.z = fmaxf(MU_C * v.z + a.z - THR_C, 0.f);
        v.w = fmaxf(MU_C * v.w + a.w - THR_C, 0.f);
    } else if (epi == EPI_RES) {
        float4 a = ((const float4*)add)[i];
        v.x = a.x - v.x; v.y = a.y - v.y; v.z = a.z - v.z; v.w = a.w - v.w;
    } else if (epi == EPI_TANH) {
        v.x = tanhf(v.x); v.y = tanhf(v.y); v.z = tanhf(v.z); v.w = tanhf(v.w);
    }
    ((float4*)out)[i] = v;
}

// ---------------------------------------------------------------------------
// Cin=3 transposed conv (fp32 direct).
// ---------------------------------------------------------------------------
__global__ __launch_bounds__(128) void conv_t_c3_k(
    const float* __restrict__ y, const float* __restrict__ w,
    float* __restrict__ out, const float* __restrict__ add,
    int N, int Cy, int OHy, int OWy, int H, int Wd, int epi)
{
    const int a = blockIdx.z >> 1, b = blockIdx.z & 1;
    const int HH = H >> 1, WW = Wd >> 1, PHW = HH * WW, Ntot = N * PHW;
    const int OHWy = OHy * OWy;
    const int kha0 = 1 - a, kwb0 = 1 - b;
    __shared__ float Wsm[768];
    const int tid = threadIdx.x;
    for (int i = tid; i < Cy * 12; i += 128) {
        int co = i / 12, r = i - co * 12, ci = r >> 2, jj = (r >> 1) & 1, ll = r & 1;
        Wsm[i] = w[(((size_t)co * 3 + ci) * 4 + (kha0 + 2 * jj)) * 4 + (kwb0 + 2 * ll)];
    }
    __syncthreads();
    int p = blockIdx.x * 128 + tid;
    if (p >= Ntot) return;
    int n = p / PHW, rem = p - n * PHW, u = rem / WW, v = rem - u * WW;
    float acc0 = 0.f, acc1 = 0.f, acc2 = 0.f;
    const int oh0 = u + a, oh1 = u + a - 1, ow0 = v + b, ow1 = v + b - 1;
    const bool h0 = (unsigned)oh0 < (unsigned)OHy, h1 = (unsigned)oh1 < (unsigned)OHy;
    const bool w0 = (unsigned)ow0 < (unsigned)OWy, w1 = (unsigned)ow1 < (unsigned)OWy;
    const float* ybase = y + (size_t)n * Cy * OHWy;
    for (int co = 0; co < Cy; co++) {
        const float* yc = ybase + (size_t)co * OHWy;
        const float* wc = &Wsm[co * 12];
        float y00 = (h0 && w0) ? yc[oh0 * OWy + ow0] : 0.f;
        float y01 = (h0 && w1) ? yc[oh0 * OWy + ow1] : 0.f;
        float y10 = (h1 && w0) ? yc[oh1 * OWy + ow0] : 0.f;
        float y11 = (h1 && w1) ? yc[oh1 * OWy + ow1] : 0.f;
        acc0 += y00 * wc[0] + y01 * wc[1] + y10 * wc[2] + y11 * wc[3];
        acc1 += y00 * wc[4] + y01 * wc[5] + y10 * wc[6] + y11 * wc[7];
        acc2 += y00 * wc[8] + y01 * wc[9] + y10 * wc[10] + y11 * wc[11];
    }
    const int HWi = H * Wd;
    size_t ob = (size_t)n * 3 * HWi + (size_t)(2 * u + a) * Wd + (2 * v + b);
    float accs[3] = {acc0, acc1, acc2};
#pragma unroll
    for (int ci = 0; ci < 3; ci++) {
        size_t idx = ob + (size_t)ci * HWi;
        out[idx] = apply_epi(accs[ci], add, idx, epi);
    }
}

// ---------------------------------------------------------------------------
// Block-6 GEMV / GEMM-T (fp32)
// ---------------------------------------------------------------------------
__global__ __launch_bounds__(256) void gemv6_k(
    const float* __restrict__ in, const float* __restrict__ w,
    float* __restrict__ out, const float* __restrict__ add, int epi)
{
    __shared__ float xs[9216];
    const int n = blockIdx.x;
    const float* xr = in + (size_t)n * 9216;
    for (int i = threadIdx.x; i < 9216; i += 256) xs[i] = xr[i];
    __syncthreads();
    const int warp = threadIdx.x >> 5, lane = threadIdx.x & 31;
    const int co = blockIdx.y * 8 + warp;
    const float* wr = w + (size_t)co * 9216;
    float s = 0.f;
    for (int k = lane; k < 9216; k += 32) s += xs[k] * wr[k];
#pragma unroll
    for (int o = 16; o; o >>= 1) s += __shfl_down_sync(0xffffffffu, s, o);
    if (lane == 0) {
        int idx = n * 128 + co;
        float v = s;
        if (epi == EPI_SHRINK) {
            float ad = add ? add[idx] : 0.f;
            v = fmaxf(MU_C * v + ad - THR_C, 0.f);
        }
        out[idx] = v;
    }
}

__global__ __launch_bounds__(256) void gemm6t_k(
    const float* __restrict__ h, const float* __restrict__ w,
    float* __restrict__ out, const float* __restrict__ add, int epi)
{
    __shared__ float hs[128];
    const int n = blockIdx.y;
    const int m = blockIdx.x * 1024 + threadIdx.x * 4;
    if (threadIdx.x < 128) hs[threadIdx.x] = h[n * 128 + threadIdx.x];
    __syncthreads();
    float4 acc = make_float4(0.f, 0.f, 0.f, 0.f);
    const float* wp = w + m;
#pragma unroll 4
    for (int co = 0; co < 128; co++) {
        float hv = hs[co];
        float4 wv = *(const float4*)(wp + (size_t)co * 9216);
        acc.x += hv * wv.x; acc.y += hv * wv.y;
        acc.z += hv * wv.z; acc.w += hv * wv.w;
    }
    size_t base = (size_t)n * 9216 + m;
    float r[4] = {acc.x, acc.y, acc.z, acc.w};
#pragma unroll
    for (int t = 0; t < 4; t++) {
        float v = r[t];
        if (epi == EPI_RES) v = add[base + t] - v;
        out[base + t] = v;
    }
}

// ---------------------------------------------------------------------------
// elementwise / reductions / weight prep
// ---------------------------------------------------------------------------
__global__ void fista_y_k(const float* __restrict__ z, const float* __restrict__ zold,
                          float c, float* __restrict__ y, int nelem)
{
    int i = blockIdx.x * blockDim.x + threadIdx.x;
    if (i < nelem) {
        float zv = z[i];
        y[i] = zv + c * (zv - zold[i]);
    }
}

__global__ void lrelu_k(const float* __restrict__ in, float* __restrict__ out, int n)
{
    int i = blockIdx.x * blockDim.x + threadIdx.x;
    if (i < n) {
        float v = in[i];
        out[i] = v >= 0.f ? v : 0.2f * v;
    }
}

__global__ __launch_bounds__(256) void bn_act_k(
    const float* __restrict__ in, float* __restrict__ out,
    int N, int C, int HW, int act)
{
    const int c = blockIdx.x;
    const int M = N * HW;
    const int tid = threadIdx.x;
    double ds = 0.0, ds2 = 0.0;
    for (int i = tid; i < M; i += 256) {
        int n = i / HW, r = i - n * HW;
        float v = in[((size_t)n * C + c) * HW + r];
        ds += v; ds2 += (double)v * v;
    }
    __shared__ double sh[512];
    sh[tid] = ds; sh[256 + tid] = ds2;
    __syncthreads();
    for (int s = 128; s > 0; s >>= 1) {
        if (tid < s) { sh[tid] += sh[tid + s]; sh[256 + tid] += sh[256 + tid + s]; }
        __syncthreads();
    }
    __shared__ float mean_s, scale_s;
    if (tid == 0) {
        double m = sh[0] / M;
        double var = sh[256] / M - m * m;
        float vf = (float)var; if (vf < 0.f) vf = 0.f;
        mean_s = (float)m;
        scale_s = 1.0f / sqrtf(vf + 1e-5f);
    }
    __syncthreads();
    float mean = mean_s, scale = scale_s;
    for (int i = tid; i < M; i += 256) {
        int n = i / HW, r = i - n * HW;
        size_t idx = ((size_t)n * C + c) * HW + r;
        float v = (in[idx] - mean) * scale;
        if (act == 1) v = v >= 0.f ? v : 0.2f * v;
        else if (act == 2) v = fmaxf(v, 0.f);
        out[idx] = v;
    }
}

__global__ __launch_bounds__(256) void wnorm_all_k(
    const float* __restrict__ W1, const float* __restrict__ W2,
    const float* __restrict__ W3, const float* __restrict__ W4,
    const float* __restrict__ W5, const float* __restrict__ W6,
    float* __restrict__ wn)
{
    const int a = blockIdx.x;  // 0..2111
    const int cum[6]  = {64, 192, 448, 960, 1984, 2112};
    const int lens[6] = {48, 1024, 2048, 4096, 8192, 9216};
    const long offs[6] = {0, 3072, 134144, 658432, 2755584, 11144192};
    int wi = 0;
    while (a >= cum[wi]) wi++;
    int local = a - (wi ? cum[wi - 1] : 0);
    const float* Ws[6] = {W1, W2, W3, W4, W5, W6};
    const int L = lens[wi];
    const float* src = Ws[wi] + (size_t)local * L;
    float* dst = wn + offs[wi] + (size_t)local * L;
    const int tid = threadIdx.x;
    float s = 0.f;
    for (int i = tid; i < L; i += 256) { float v = src[i]; s += v * v; }
    __shared__ float sh[256];
    sh[tid] = s; __syncthreads();
    for (int sf = 128; sf > 0; sf >>= 1) {
        if (tid < sf) sh[tid] += sh[tid + sf];
        __syncthreads();
    }
    float inv = 1.0f / (sqrtf(sh[0]) + 1e-12f);
    for (int i = tid; i < L; i += 256) dst[i] = src[i] * inv;
}

// bf16 hi/lo copies (fwd K-major) + per-parity transposed convT weights.
__global__ void wprep_k(const float* __restrict__ wn,
                        __nv_bfloat16* __restrict__ wh, __nv_bfloat16* __restrict__ wl,
                        __nv_bfloat16* __restrict__ wth, __nv_bfloat16* __restrict__ wtl)
{
    int i0 = blockIdx.x * 256 + threadIdx.x;
    int stride = gridDim.x * 256;
    for (int t = i0; t < 12323840; t += stride) {
        float v = wn[t];
        __nv_bfloat16 h = __float2bfloat16(v);
        wh[t] = h;
        wl[t] = __float2bfloat16(v - __bfloat162float(h));
    }
    const int cum[4] = {131072, 655360, 2752512, 11141120};
    const int cins[4] = {64, 128, 256, 512};
    const long woffs[4] = {3072, 134144, 658432, 2755584};
    for (int t = i0; t < 11141120; t += stride) {
        int wi = 0;
        while (t >= cum[wi]) wi++;
        int local = t - (wi ? cum[wi - 1] : 0);
        int Cin = cins[wi], Kd = 8 * Cin;   // Cout = 2*Cin -> Kdim = 4*Cout
        int per = Cin * Kd;
        int par = local / per, rem = local - par * per;
        int ci = rem / Kd, k = rem - ci * Kd;
        int co = k >> 2, jj = (k >> 1) & 1, ll = k & 1;
        int kha = 1 - (par >> 1) + 2 * jj, kwb = 1 - (par & 1) + 2 * ll;
        float v = wn[woffs[wi] + ((size_t)co * Cin + ci) * 16 + kha * 4 + kwb];
        __nv_bfloat16 h = __float2bfloat16(v);
        wth[t] = h;
        wtl[t] = __float2bfloat16(v - __bfloat162float(h));
    }
}

__global__ void znorm_k(const float* __restrict__ z, float* __restrict__ out)
{
    const int n = blockIdx.x;
    const int t = threadIdx.x;
    float v = z[n * 128 + t];
    __shared__ float sh[128];
    sh[t] = v * v; __syncthreads();
    for (int s = 64; s > 0; s >>= 1) {
        if (t < s) sh[t] += sh[t + s];
        __syncthreads();
    }
    float denom = fmaxf(sqrtf(sh[0]), 1e-12f);
    out[n * 128 + t] = v / denom;
}

// ---------------------------------------------------------------------------
// Host orchestration
// ---------------------------------------------------------------------------
static inline int cdiv(int a, int b) { return (a + b - 1) / b; }
static float* g_sp = nullptr;

static int pick_S(int base, int chunks, long nelem)
{
    int S = 1;
    while (base * S < 280 && S < 8) S <<= 1;
    while (S > 1 && (chunks % S)) S >>= 1;
    while (S > 1 && nelem * S > 9437184L) S >>= 1;
    return S;
}

static void launch_fwd(const float* in, const __nv_bfloat16* wh, const __nv_bfloat16* wl,
                       float* out, const float* add,
                       int N, int Cin, int H, int Wd, int Cout, int OH, int OW, int epi)
{
    int bx = cdiv(Cout, 128), by = cdiv(N * OH * OW, 64);
    int chunks = cdiv(Cin * 16, 32); if (chunks < 1) chunks = 1;
    long nelem = (long)N * Cout * OH * OW;
    int S = pick_S(bx * by, chunks, nelem);
    if (S == 1) {
        conv_wm<<<dim3(bx, by, 1), 256, SMEM_WM>>>(in, wh, wl, out, add,
            N, Cin, H, Wd, Cout, OH, OW, epi, chunks, 0, 0, 0);
    } else {
        conv_wm<<<dim3(bx, by, S), 256, SMEM_WM>>>(in, wh, wl, g_sp, nullptr,
            N, Cin, H, Wd, Cout, OH, OW, epi, chunks / S, (int)nelem, 1, 0);
        reduce_epi_k<<<cdiv((int)(nelem / 4), 256), 256>>>(g_sp, S, (int)(nelem / 4), out, add, epi);
    }
}

static void launch_t(const float* y, const __nv_bfloat16* wth, const __nv_bfloat16* wtl,
                     const float* wfp, float* out, const float* add,
                     int N, int Cy, int OHy, int OWy, int Cin, int H, int Wd, int epi)
{
    int NtotP = N * (H / 2) * (Wd / 2);
    if (Cin == 3) {
        conv_t_c3_k<<<dim3(cdiv(NtotP, 128), 1, 4), 128>>>(y, wfp, out, add,
            N, Cy, OHy, OWy, H, Wd, epi);
        return;
    }
    int bx = cdiv(Cin, 128), by = cdiv(NtotP, 64);
    int chunks = Cy / 8;                // Kdim(=Cy*4)/32
    long nelem = (long)N * Cin * H * Wd;
    int S = pick_S(bx * by * 4, chunks, nelem);
    if (S == 1) {
        conv_wm<<<dim3(bx, by, 4), 256, SMEM_WM>>>(y, wth, wtl, out, add,
            N, Cy, OHy, OWy, Cin, H, Wd, epi, chunks, 0, 0, 1);
    } else {
        conv_wm<<<dim3(bx, by, 4 * S), 256, SMEM_WM>>>(y, wth, wtl, g_sp, nullptr,
            N, Cy, OHy, OWy, Cin, H, Wd, epi, chunks / S, (int)nelem, 1, 1);
        reduce_epi_k<<<cdiv((int)(nelem / 4), 256), 256>>>(g_sp, S, (int)(nelem / 4), out, add, epi);
    }
}

extern "C" void kernel_launch(void* const* d_in, const int* in_sizes, int n_in,
                              void* d_out, int out_size)
{
    const float* x = (const float*)d_in[0];
    const float* W[6];
    for (int i = 0; i < 6; i++) W[i] = (const float*)d_in[1 + i];
    float* out = (float*)d_out;

    float *z1, *z2, *z3, *rb, *actb, *wn, *sp;
    __nv_bfloat16 *wh, *wl, *wth, *wtl;
    cudaGetSymbolAddress((void**)&z1, g_z1);
    cudaGetSymbolAddress((void**)&z2, g_z2);
    cudaGetSymbolAddress((void**)&z3, g_z3);
    cudaGetSymbolAddress((void**)&rb, g_r);
    cudaGetSymbolAddress((void**)&actb, g_act);
    cudaGetSymbolAddress((void**)&wn, g_wn);
    cudaGetSymbolAddress((void**)&sp, g_split);
    cudaGetSymbolAddress((void**)&wh, g_wh);
    cudaGetSymbolAddress((void**)&wl, g_wl);
    cudaGetSymbolAddress((void**)&wth, g_wth);
    cudaGetSymbolAddress((void**)&wtl, g_wtl);
    g_sp = sp;
    // conv_wm uses 61 KB dynamic smem -> raise the default 48 KB cap.
    cudaFuncSetAttribute(conv_wm, cudaFuncAttributeMaxDynamicSharedMemorySize, SMEM_WM);

    const size_t woff[6] = {0, 3072, 134144, 658432, 2755584, 11144192};
    const size_t toff[5] = {0, 0, 131072, 655360, 2752512};  // indexed by wi (1..4)

    wnorm_all_k<<<2112, 256>>>(W[0], W[1], W[2], W[3], W[4], W[5], wn);
    wprep_k<<<2048, 256>>>(wn, wh, wl, wth, wtl);

    struct Stg { int Cin, H, Cout, OH, wi; };
    const Stg st[5] = {
        {3, 96, 64, 48, 0}, {64, 48, 128, 24, 1}, {128, 24, 256, 12, 2},
        {256, 12, 512, 6, 3}, {512, 6, 1024, 3, 4},
    };

    const float* cur = x;
    for (int s = 0; s < 5; s++) {
        const Stg& S = st[s];
        const __nv_bfloat16* whp = wh + woff[S.wi];
        const __nv_bfloat16* wlp = wl + woff[S.wi];
        const int OW = S.OH, Wd = S.H;
        const int zn = 64 * S.Cout * S.OH * OW;

        launch_fwd(cur, whp, wlp, z1, nullptr, 64, S.Cin, S.H, Wd, S.Cout, S.OH, OW, EPI_SHRINK);
        float* zc = z1; float* zo = z1;
        double t = 1.0;
        for (int it = 0; it < 3; it++) {
            double tn = (1.0 + sqrt(1.0 + 4.0 * t * t)) * 0.5;
            float c = (float)((t - 1.0) / tn);
            t = tn;
            const float* yp;
            if (it == 0) yp = zc;
            else {
                fista_y_k<<<cdiv(zn, 256), 256>>>(zc, zo, c, z3, zn);
                yp = z3;
            }
            launch_t(yp, wth + toff[S.wi], wtl + toff[S.wi], wn + woff[S.wi],
                     rb, cur, 64, S.Cout, S.OH, OW, S.Cin, S.H, Wd, EPI_RES);
            float* znew = (it == 0) ? z2 : zo;
            launch_fwd(rb, whp, wlp, znew, yp, 64, S.Cin, S.H, Wd, S.Cout, S.OH, OW, EPI_SHRINK);
            zo = zc; zc = znew;
        }
        if (s == 0) lrelu_k<<<cdiv(zn, 256), 256>>>(zc, actb, zn);
        else        bn_act_k<<<S.Cout, 256>>>(zc, actb, 64, S.Cout, S.OH * OW, 1);
        cur = actb;
    }

    // block 6 (3x3 s1 p0 -> GEMM)
    {
        const float* w6 = wn + woff[5];
        const int zn = 64 * 128;
        gemv6_k<<<dim3(64, 16), 256>>>(cur, w6, z1, nullptr, EPI_SHRINK);
        float* zc = z1; float* zo = z1;
        double t = 1.0;
        for (int it = 0; it < 3; it++) {
            double tn = (1.0 + sqrt(1.0 + 4.0 * t * t)) * 0.5;
            float c = (float)((t - 1.0) / tn);
            t = tn;
            const float* yp;
            if (it == 0) yp = zc;
            else {
                fista_y_k<<<cdiv(zn, 256), 256>>>(zc, zo, c, z3, zn);
                yp = z3;
            }
            gemm6t_k<<<dim3(9, 64), 256>>>(yp, w6, rb, cur, EPI_RES);
            float* znew = (it == 0) ? z2 : zo;
            gemv6_k<<<dim3(64, 16), 256>>>(rb, w6, znew, yp, EPI_SHRINK);
            zo = zc; zc = znew;
        }
        znorm_k<<<64, 128>>>(zc, out);
    }

    // decoder
    {
        const float* w6 = wn + woff[5];
        gemm6t_k<<<dim3(9, 64), 256>>>(out, w6, z1, nullptr, EPI_NONE);
        bn_act_k<<<1024, 256>>>(z1, z1, 64, 1024, 9, 2);

        struct DS { int Cy, OHy, Cin, H, wi; };
        const DS ds[4] = {
            {1024, 3, 512, 6, 4}, {512, 6, 256, 12, 3},
            {256, 12, 128, 24, 2}, {128, 24, 64, 48, 1},
        };
        float* hin = z1; float* hout = z2;
        for (int i = 0; i < 4; i++) {
            const DS& D = ds[i];
            launch_t(hin, wth + toff[D.wi], wtl + toff[D.wi], wn + woff[D.wi],
                     hout, nullptr, 64, D.Cy, D.OHy, D.OHy, D.Cin, D.H, D.H, EPI_NONE);
            bn_act_k<<<D.Cin, 256>>>(hout, hout, 64, D.Cin, D.H * D.H, 2);
            float* tmp = hin; hin = hout; hout = tmp;
        }
        launch_t(hin, nullptr, nullptr, wn + woff[0], out + 8192, nullptr,
                 64, 64, 48, 48, 3, 96, 96, EPI_TANH);
    }
}